// round 1
// baseline (speedup 1.0000x reference)
#include <cuda_runtime.h>
#include <cstdint>

// Problem dims (fixed by the dataset)
#define BB 2
#define LL 1024
#define HH 8
#define EE 64
#define NBH (BB*HH)

typedef unsigned long long ull;

// 64 MiB scratch for the raw score matrix G[bh][l][s] (pre-elementwise).
__device__ float g_scores[(size_t)NBH * LL * LL];
// Fallbacks in case d_out only holds V (defensive vs. output-layout surprises).
__device__ float g_att_fb[(size_t)NBH * LL * LL];
__device__ float g_ent_fb[(size_t)NBH * LL];

// ---- packed f32x2 helpers (FFMA2 path: 2 MACs per FMA-pipe issue) ----
__device__ __forceinline__ ull pack2(float lo, float hi) {
    ull r; asm("mov.b64 %0, {%1, %2};" : "=l"(r) : "f"(lo), "f"(hi)); return r;
}
__device__ __forceinline__ ull dup2(float x) {
    ull r; asm("mov.b64 %0, {%1, %1};" : "=l"(r) : "f"(x)); return r;
}
__device__ __forceinline__ ull ffma2(ull a, ull b, ull c) {
    ull d; asm("fma.rn.f32x2 %0, %1, %2, %3;" : "=l"(d) : "l"(a), "l"(b), "l"(c)); return d;
}
__device__ __forceinline__ float2 unpk2(ull v) {
    float2 f; asm("mov.b64 {%0, %1}, %2;" : "=f"(f.x), "=f"(f.y) : "l"(v)); return f;
}

// ============================================================================
// K1: G[bh][l][s] = (1/8) * sum_e q[b,l,h,e]*k[b,s,h,e]
// grid (16 s-tiles, 16 l-tiles, 16 bh), 64 threads, 64x64 tile, K=64 resident.
// smem is k-major ([e][row]) so micro-tile fragments are contiguous float4s.
// ============================================================================
__global__ __launch_bounds__(64) void k1_scores(const float* __restrict__ q,
                                                const float* __restrict__ k) {
    __shared__ float Qs[EE][68];
    __shared__ float Ks[EE][68];
    const int bh = blockIdx.z, b = bh >> 3, h = bh & 7;
    const int lb = blockIdx.y << 6;
    const int sb = blockIdx.x << 6;
    const int tid = threadIdx.x;

    #pragma unroll
    for (int t = tid; t < 64 * 16; t += 64) {
        int row = t >> 4, e4 = (t & 15) << 2;
        float4 qv = *(const float4*)(q + (((size_t)(b * LL + lb + row)) * HH + h) * EE + e4);
        Qs[e4 + 0][row] = qv.x; Qs[e4 + 1][row] = qv.y;
        Qs[e4 + 2][row] = qv.z; Qs[e4 + 3][row] = qv.w;
        float4 kv = *(const float4*)(k + (((size_t)(b * LL + sb + row)) * HH + h) * EE + e4);
        Ks[e4 + 0][row] = kv.x; Ks[e4 + 1][row] = kv.y;
        Ks[e4 + 2][row] = kv.z; Ks[e4 + 3][row] = kv.w;
    }
    __syncthreads();

    const int l0 = (tid >> 3) << 3;
    const int s0 = (tid & 7) << 3;

    ull acc[8][4];
    #pragma unroll
    for (int r = 0; r < 8; r++)
        #pragma unroll
        for (int c = 0; c < 4; c++) acc[r][c] = 0ull;

    #pragma unroll 16
    for (int e = 0; e < EE; e++) {
        float4 a0 = *(const float4*)&Qs[e][l0];
        float4 a1 = *(const float4*)&Qs[e][l0 + 4];
        float4 b0 = *(const float4*)&Ks[e][s0];
        float4 b1 = *(const float4*)&Ks[e][s0 + 4];
        ull bp[4];
        bp[0] = pack2(b0.x, b0.y); bp[1] = pack2(b0.z, b0.w);
        bp[2] = pack2(b1.x, b1.y); bp[3] = pack2(b1.z, b1.w);
        float av[8] = {a0.x, a0.y, a0.z, a0.w, a1.x, a1.y, a1.z, a1.w};
        #pragma unroll
        for (int r = 0; r < 8; r++) {
            ull ad = dup2(av[r]);
            #pragma unroll
            for (int c = 0; c < 4; c++) acc[r][c] = ffma2(ad, bp[c], acc[r][c]);
        }
    }

    float* grow = g_scores + ((size_t)bh << 20);
    #pragma unroll
    for (int r = 0; r < 8; r++) {
        float o[8];
        #pragma unroll
        for (int c = 0; c < 4; c++) {
            float2 f = unpk2(acc[r][c]);
            o[2 * c] = f.x * 0.125f; o[2 * c + 1] = f.y * 0.125f;
        }
        float* p = grow + (size_t)(lb + l0 + r) * LL + sb + s0;
        *(float4*)p       = make_float4(o[0], o[1], o[2], o[3]);
        *(float4*)(p + 4) = make_float4(o[4], o[5], o[6], o[7]);
    }
}

// ============================================================================
// K2: elementwise att tile. Block owns att[lb:lb+64, sb:sb+64] of one bh.
// Reads G[l,s] and G[s,l] tiles (both row-coalesced from gmem into smem).
// ============================================================================
__global__ __launch_bounds__(256) void k2_att(float* __restrict__ att,
                                              const float* __restrict__ p_lgg,
                                              const float* __restrict__ p_ltg,
                                              const float* __restrict__ p_lgd,
                                              const float* __restrict__ p_ltd) {
    __shared__ float G1s[64][65];   // G[lb+r][sb+c]
    __shared__ float G2s[64][65];   // G[sb+r][lb+c]  (accessed transposed)
    const int bh = blockIdx.z;
    const int lb = blockIdx.y << 6;
    const int sb = blockIdx.x << 6;
    const float* G = g_scores + ((size_t)bh << 20);
    const int tid = threadIdx.x;

    #pragma unroll
    for (int t = tid; t < 64 * 16; t += 256) {
        int r = t >> 4, c4 = (t & 15) << 2;
        float4 v1 = *(const float4*)(G + (size_t)(lb + r) * LL + sb + c4);
        G1s[r][c4] = v1.x; G1s[r][c4 + 1] = v1.y; G1s[r][c4 + 2] = v1.z; G1s[r][c4 + 3] = v1.w;
        float4 v2 = *(const float4*)(G + (size_t)(sb + r) * LL + lb + c4);
        G2s[r][c4] = v2.x; G2s[r][c4 + 1] = v2.y; G2s[r][c4 + 2] = v2.z; G2s[r][c4 + 3] = v2.w;
    }
    __syncthreads();

    // learned scalar params (exp + clip, as in reference)
    const float gg = fminf(fmaxf(expf(*p_lgg), 1e-3f), 20.0f);
    const float tg = fminf(fmaxf(expf(*p_ltg), 1e-3f), 10.0f);
    const float gd = fminf(fmaxf(expf(*p_lgd), 1e-3f), 20.0f);
    const float td = fminf(fmaxf(expf(*p_ltd), 1e-3f), 10.0f);
    const float itg = 1.0f / tg;
    const float itd = 1.0f / td;
    const float gdd = gd / td;

    const int l  = tid >> 2;
    const int s0 = (tid & 3) << 4;
    const int lg = lb + l;
    float* arow = att + ((size_t)bh * LL + lg) * LL + sb;

    #pragma unroll
    for (int u = 0; u < 4; u++) {
        float o[4];
        #pragma unroll
        for (int v = 0; v < 4; v++) {
            int s = s0 + u * 4 + v;
            float g1 = G1s[l][s];
            float g2 = G2s[s][l];
            float Ssym = 0.5f * (g1 + g2);
            float Aant = 0.5f * (g1 - g2);
            float gate = 1.0f / (1.0f + expf(-(gg * tanhf(Ssym * itg))));
            float dir  = 1.0f / (1.0f + expf(-(gd * tanhf(Aant * itd))));
            float m = gate * dir;
            if (lg == sb + s) m = 0.0f;   // zero diagonal (P(i->i)=0)
            o[v] = fmaxf(tanhf(Aant * gdd), 0.0f) * m;
        }
        *(float4*)(arow + s0 + u * 4) = make_float4(o[0], o[1], o[2], o[3]);
    }
}

// ============================================================================
// K3: V[b,l,h,:] = sum_s att[bh,l,s]*value[b,s,h,:]  +  entropy[bh,l]
// grid (8 l-tiles, 16 bh), 128 threads, l-tile=128 rows, full E=64,
// s streamed in chunks of 32. Entropy fused (row tid), no atomics needed.
// ============================================================================
__global__ __launch_bounds__(128) void k3_av(const float* __restrict__ att,
                                             const float* __restrict__ val,
                                             float* __restrict__ vout,
                                             float* __restrict__ ent) {
    __shared__ float As[128][33];
    __shared__ float Vs[32][68];
    const int bh = blockIdx.y, b = bh >> 3, h = bh & 7;
    const int lb = blockIdx.x << 7;
    const int tid = threadIdx.x;
    const int eg = tid & 7, lgp = tid >> 3;
    const int lrow0 = lgp << 3;
    const int e0 = eg << 3;

    ull acc[8][4];
    #pragma unroll
    for (int r = 0; r < 8; r++)
        #pragma unroll
        for (int c = 0; c < 4; c++) acc[r][c] = 0ull;
    float entacc = 0.0f;

    const float* attbase = att + ((size_t)bh * LL + lb) * LL;

    for (int cb = 0; cb < 32; cb++) {
        const int sb = cb << 5;
        __syncthreads();
        #pragma unroll
        for (int t = tid; t < 128 * 8; t += 128) {
            int r = t >> 3, c4 = (t & 7) << 2;
            float4 v = *(const float4*)(attbase + (size_t)r * LL + sb + c4);
            As[r][c4] = v.x; As[r][c4 + 1] = v.y; As[r][c4 + 2] = v.z; As[r][c4 + 3] = v.w;
        }
        #pragma unroll
        for (int t = tid; t < 32 * 16; t += 128) {
            int r = t >> 4, c4 = (t & 15) << 2;
            float4 v = *(const float4*)(val + (((size_t)(b * LL + sb + r)) * HH + h) * EE + c4);
            Vs[r][c4] = v.x; Vs[r][c4 + 1] = v.y; Vs[r][c4 + 2] = v.z; Vs[r][c4 + 3] = v.w;
        }
        __syncthreads();

        #pragma unroll 4
        for (int ss = 0; ss < 32; ss++) {
            float4 w0 = *(const float4*)&Vs[ss][e0];
            float4 w1 = *(const float4*)&Vs[ss][e0 + 4];
            ull v2[4];
            v2[0] = pack2(w0.x, w0.y); v2[1] = pack2(w0.z, w0.w);
            v2[2] = pack2(w1.x, w1.y); v2[3] = pack2(w1.z, w1.w);
            #pragma unroll
            for (int r = 0; r < 8; r++) {
                ull ad = dup2(As[lrow0 + r][ss]);
                #pragma unroll
                for (int c = 0; c < 4; c++) acc[r][c] = ffma2(ad, v2[c], acc[r][c]);
            }
        }
        // entropy partial: this thread owns att row (lb+tid); conflict-free (pitch 33)
        #pragma unroll
        for (int ss = 0; ss < 32; ss++) {
            float a = As[tid][ss];
            entacc += a * __logf(fmaxf(a, 1e-8f));   // a==0 contributes exactly 0
        }
    }

    ent[(size_t)bh * LL + lb + tid] = -entacc;

    #pragma unroll
    for (int r = 0; r < 8; r++) {
        int l = lb + lrow0 + r;
        float o[8];
        #pragma unroll
        for (int c = 0; c < 4; c++) {
            float2 f = unpk2(acc[r][c]);
            o[2 * c] = f.x; o[2 * c + 1] = f.y;
        }
        float* p = vout + (((size_t)(b * LL + l)) * HH + h) * EE + e0;
        *(float4*)p       = make_float4(o[0], o[1], o[2], o[3]);
        *(float4*)(p + 4) = make_float4(o[4], o[5], o[6], o[7]);
    }
}

// ============================================================================
// Launch: K1 -> K2 -> K3 on the default stream (order = dependency).
// Graph-capturable: kernel launches only; no sync, no alloc.
// ============================================================================
extern "C" void kernel_launch(void* const* d_in, const int* in_sizes, int n_in,
                              void* d_out, int out_size) {
    const float* q = (const float*)d_in[0];
    const float* k = (const float*)d_in[1];
    const float* v = (const float*)d_in[2];
    // learned scalars are the LAST four inputs (robust to middle-input quirks)
    const float* lgg = (const float*)d_in[n_in - 4];
    const float* ltg = (const float*)d_in[n_in - 3];
    const float* lgd = (const float*)d_in[n_in - 2];
    const float* ltd = (const float*)d_in[n_in - 1];

    const long V_ELEMS   = (long)BB * LL * HH * EE;         // 1,048,576
    const long ATT_ELEMS = (long)NBH * LL * LL;             // 16,777,216
    const long ENT_ELEMS = (long)NBH * LL;                  // 16,384

    float* out  = (float*)d_out;
    float* vptr = out;
    float* attp;
    float* entp;
    if ((long)out_size >= V_ELEMS + ATT_ELEMS + ENT_ELEMS) {
        attp = out + V_ELEMS;
        entp = out + V_ELEMS + ATT_ELEMS;
    } else {
        // Output smaller than full tuple: keep att/entropy in device scratch.
        void* p1 = nullptr; void* p2 = nullptr;
        cudaGetSymbolAddress(&p1, g_att_fb);
        cudaGetSymbolAddress(&p2, g_ent_fb);
        attp = (float*)p1;
        entp = (float*)p2;
    }

    k1_scores<<<dim3(16, 16, 16), 64>>>(q, k);
    k2_att<<<dim3(16, 16, 16), 256>>>(attp, lgg, ltg, lgd, ltd);
    k3_av<<<dim3(8, 16), 128>>>(attp, v, vptr, entp);
}

// round 2
// speedup vs baseline: 1.3858x; 1.3858x over previous
#include <cuda_runtime.h>
#include <cstdint>

#define LLEN 1024
#define NBH 16

typedef unsigned long long ull;

// Fallbacks in case d_out only holds V (defensive vs. output-layout surprises).
__device__ float g_att_fb[(size_t)NBH * LLEN * LLEN];
__device__ float g_ent_fb[(size_t)NBH * LLEN];

// ---- packed f32x2 helpers (FFMA2: 2 MACs per FMA-pipe issue) ----
__device__ __forceinline__ ull pack2(float lo, float hi) {
    ull r; asm("mov.b64 %0, {%1, %2};" : "=l"(r) : "f"(lo), "f"(hi)); return r;
}
__device__ __forceinline__ ull dup2(float x) {
    ull r; asm("mov.b64 %0, {%1, %1};" : "=l"(r) : "f"(x)); return r;
}
__device__ __forceinline__ ull ffma2(ull a, ull b, ull c) {
    ull d; asm("fma.rn.f32x2 %0, %1, %2, %3;" : "=l"(d) : "l"(a), "l"(b), "l"(c)); return d;
}
__device__ __forceinline__ float2 unpk2(ull v) {
    float2 f; asm("mov.b64 {%0, %1}, %2;" : "=f"(f.x), "=f"(f.y) : "l"(v)); return f;
}
// MUFU.TANH (sm_75+): 1 instruction vs ~25 for accurate tanhf
__device__ __forceinline__ float tanha(float x) {
    float y; asm("tanh.approx.f32 %0, %1;" : "=f"(y) : "f"(x)); return y;
}

// ============================================================================
// Fused kernel A: for tile pair (i,j), j<=i, of one bh:
//   C1 = scale*Q_i K_j^T, C2 = scale*Q_j K_i^T  (both in smem)
//   att tile (i,j) from (C1, C2^T); att tile (j,i) from (C2, C1^T).
// 128 threads: half 0 -> C1 (8x8 micro each), half 1 -> C2.
// E=64 processed in two 32-wide chunks (smem budget).
// ============================================================================
__global__ __launch_bounds__(128) void kA(const float* __restrict__ q,
                                          const float* __restrict__ kk,
                                          float* __restrict__ att,
                                          const float* __restrict__ p0,
                                          const float* __restrict__ p1,
                                          const float* __restrict__ p2,
                                          const float* __restrict__ p3) {
    __shared__ float sb_[8704];   // phase1: 4x[32][68]; phase2: 2x[64][68]
    const int p = blockIdx.x, bh = blockIdx.y;
    const int b = bh >> 3, h = bh & 7;
    // triangular pair decode: p -> (i,j), j<=i
    int i = (int)((__fsqrt_rn(8.0f * p + 1.0f) - 1.0f) * 0.5f);
    while ((i + 1) * (i + 2) / 2 <= p) i++;
    while (i * (i + 1) / 2 > p) i--;
    const int j = p - i * (i + 1) / 2;

    const int tid = threadIdx.x;
    const int half = tid >> 6, t6 = tid & 63;
    const int l0 = (t6 >> 3) << 3, s0 = (t6 & 7) << 3;

    float* Qi = sb_;            // [32][68] each, k-major [e][row]
    float* Kj = sb_ + 2176;
    float* Qj = sb_ + 4352;
    float* Ki = sb_ + 6528;
    const float* A_ = half ? Qj : Qi;
    const float* B_ = half ? Ki : Kj;

    ull acc[8][4];
    #pragma unroll
    for (int r = 0; r < 8; r++)
        #pragma unroll
        for (int c = 0; c < 4; c++) acc[r][c] = 0ull;

    for (int c = 0; c < 2; c++) {
        __syncthreads();
        const int e0c = c << 5;
        #pragma unroll
        for (int t = tid; t < 2048; t += 128) {
            int tile = t >> 9, r = (t >> 3) & 63, e4 = (t & 7) << 2;
            int row; const float* src; float* dst;
            if (tile == 0)      { row = i * 64 + r; src = q;  dst = Qi; }
            else if (tile == 1) { row = j * 64 + r; src = kk; dst = Kj; }
            else if (tile == 2) { row = j * 64 + r; src = q;  dst = Qj; }
            else                { row = i * 64 + r; src = kk; dst = Ki; }
            float4 v = *(const float4*)(src + (((size_t)(b * LLEN + row)) * 8 + h) * 64 + e0c + e4);
            dst[(e4 + 0) * 68 + r] = v.x; dst[(e4 + 1) * 68 + r] = v.y;
            dst[(e4 + 2) * 68 + r] = v.z; dst[(e4 + 3) * 68 + r] = v.w;
        }
        __syncthreads();
        #pragma unroll 8
        for (int e = 0; e < 32; e++) {
            float4 a0 = *(const float4*)(A_ + e * 68 + l0);
            float4 a1 = *(const float4*)(A_ + e * 68 + l0 + 4);
            float4 b0 = *(const float4*)(B_ + e * 68 + s0);
            float4 b1 = *(const float4*)(B_ + e * 68 + s0 + 4);
            ull bp[4] = {pack2(b0.x, b0.y), pack2(b0.z, b0.w),
                         pack2(b1.x, b1.y), pack2(b1.z, b1.w)};
            float av[8] = {a0.x, a0.y, a0.z, a0.w, a1.x, a1.y, a1.z, a1.w};
            #pragma unroll
            for (int r = 0; r < 8; r++) {
                ull ad = dup2(av[r]);
                #pragma unroll
                for (int cc = 0; cc < 4; cc++) acc[r][cc] = ffma2(ad, bp[cc], acc[r][cc]);
            }
        }
    }

    __syncthreads();
    // write scaled score tiles into smem (reuse phase1 space)
    float* C1 = sb_;            // [64][68]
    float* C2 = sb_ + 4352;
    float* Cm = half ? C2 : C1;
    #pragma unroll
    for (int r = 0; r < 8; r++) {
        float o[8];
        #pragma unroll
        for (int cc = 0; cc < 4; cc++) {
            float2 f = unpk2(acc[r][cc]);
            o[2 * cc] = f.x * 0.125f; o[2 * cc + 1] = f.y * 0.125f;
        }
        float* pd = Cm + (l0 + r) * 68 + s0;
        *(float4*)pd       = make_float4(o[0], o[1], o[2], o[3]);
        *(float4*)(pd + 4) = make_float4(o[4], o[5], o[6], o[7]);
    }
    __syncthreads();

    // learned scalar params (exp + clip, as in reference)
    const float gg = fminf(fmaxf(__expf(*p0), 1e-3f), 20.0f);
    const float tg = fminf(fmaxf(__expf(*p1), 1e-3f), 10.0f);
    const float gd = fminf(fmaxf(__expf(*p2), 1e-3f), 20.0f);
    const float td = fminf(fmaxf(__expf(*p3), 1e-3f), 10.0f);
    const float itg = 1.0f / tg, itd = 1.0f / td, gdd = gd / td;

    // phase2: each thread owns one full att row (64 cols).
    // For i==j, C2==C1: half 1 would duplicate the same tile -> skip.
    if (!(half && i == j)) {
        const int r = t6;
        const float* Cown = half ? C2 : C1;
        const float* Coth = half ? C1 : C2;
        const int lg  = (half ? j : i) * 64 + r;
        const int sg0 = (half ? i : j) * 64;
        float* arow = att + ((size_t)bh * LLEN + lg) * LLEN + sg0;
        const bool dg = (i == j);
        #pragma unroll
        for (int s4 = 0; s4 < 64; s4 += 4) {
            float4 g1 = *(const float4*)(Cown + r * 68 + s4);
            float o[4];
            #pragma unroll
            for (int v = 0; v < 4; v++) {
                float g1v = (&g1.x)[v];
                float g2v = Coth[(s4 + v) * 68 + r];
                float Ss = 0.5f * (g1v + g2v);
                float Aa = 0.5f * (g1v - g2v);
                float t1 = tanha(Ss * itg);
                float t2 = tanha(Aa * itd);
                float s1 = fmaf(tanha(0.5f * gg * t1), 0.5f, 0.5f);  // sigmoid(gg*t1)
                float s2 = fmaf(tanha(0.5f * gd * t2), 0.5f, 0.5f);  // sigmoid(gd*t2)
                float m = s1 * s2;
                if (dg && (s4 + v) == r) m = 0.0f;   // P(i->i) = 0
                o[v] = fmaxf(tanha(Aa * gdd), 0.0f) * m;
            }
            *(float4*)(arow + s4) = make_float4(o[0], o[1], o[2], o[3]);
        }
    }
}

// ============================================================================
// K3: V[b,l,h,:] = sum_s att[bh,l,s]*value[b,s,h,:]  +  fused entropy[bh,l]
// l-tile 128 rows, s streamed in chunks of 32, 8x8 micro, f32x2 FMAs.
// ss4-batched float4 A-fragment loads (4x fewer LDS instructions).
// ============================================================================
__global__ __launch_bounds__(128) void k3_av(const float* __restrict__ att,
                                             const float* __restrict__ val,
                                             float* __restrict__ vout,
                                             float* __restrict__ ent) {
    __shared__ float As[128][36];
    __shared__ float Vs[32][68];
    const int bh = blockIdx.y, b = bh >> 3, h = bh & 7;
    const int lb = blockIdx.x << 7;
    const int tid = threadIdx.x;
    const int eg = tid & 7, lgp = tid >> 3;
    const int lrow0 = lgp << 3, e0 = eg << 3;

    ull acc[8][4];
    #pragma unroll
    for (int r = 0; r < 8; r++)
        #pragma unroll
        for (int c = 0; c < 4; c++) acc[r][c] = 0ull;
    float entacc = 0.0f;

    const float* attbase = att + ((size_t)bh * LLEN + lb) * LLEN;

    for (int cb = 0; cb < 32; cb++) {
        const int sb = cb << 5;
        __syncthreads();
        #pragma unroll
        for (int t = tid; t < 1024; t += 128) {
            int rr = t >> 3, c4 = (t & 7) << 2;
            *(float4*)&As[rr][c4] = *(const float4*)(attbase + (size_t)rr * LLEN + sb + c4);
        }
        #pragma unroll
        for (int t = tid; t < 512; t += 128) {
            int rr = t >> 4, c4 = (t & 15) << 2;
            *(float4*)&Vs[rr][c4] = *(const float4*)(val + (((size_t)(b * LLEN + sb + rr)) * 8 + h) * 64 + c4);
        }
        __syncthreads();

        #pragma unroll
        for (int s4 = 0; s4 < 32; s4 += 4) {
            float4 a4[8];
            #pragma unroll
            for (int r = 0; r < 8; r++) a4[r] = *(const float4*)&As[lrow0 + r][s4];
            #pragma unroll
            for (int u = 0; u < 4; u++) {
                int ss = s4 + u;
                float4 w0 = *(const float4*)&Vs[ss][e0];
                float4 w1 = *(const float4*)&Vs[ss][e0 + 4];
                ull v2[4] = {pack2(w0.x, w0.y), pack2(w0.z, w0.w),
                             pack2(w1.x, w1.y), pack2(w1.z, w1.w)};
                #pragma unroll
                for (int r = 0; r < 8; r++) {
                    ull ad = dup2((&a4[r].x)[u]);
                    #pragma unroll
                    for (int c = 0; c < 4; c++) acc[r][c] = ffma2(ad, v2[c], acc[r][c]);
                }
            }
        }
        // entropy partial: this thread owns att row (lb+tid)
        #pragma unroll
        for (int s4 = 0; s4 < 32; s4 += 4) {
            float4 a = *(const float4*)&As[tid][s4];
            entacc += a.x * __logf(fmaxf(a.x, 1e-8f));
            entacc += a.y * __logf(fmaxf(a.y, 1e-8f));
            entacc += a.z * __logf(fmaxf(a.z, 1e-8f));
            entacc += a.w * __logf(fmaxf(a.w, 1e-8f));
        }
    }

    ent[(size_t)bh * LLEN + lb + tid] = -entacc;

    #pragma unroll
    for (int r = 0; r < 8; r++) {
        int l = lb + lrow0 + r;
        float o[8];
        #pragma unroll
        for (int c = 0; c < 4; c++) {
            float2 f = unpk2(acc[r][c]);
            o[2 * c] = f.x; o[2 * c + 1] = f.y;
        }
        float* pd = vout + (((size_t)(b * LLEN + l)) * 8 + h) * 64 + e0;
        *(float4*)pd       = make_float4(o[0], o[1], o[2], o[3]);
        *(float4*)(pd + 4) = make_float4(o[4], o[5], o[6], o[7]);
    }
}

// ============================================================================
// Launch: kA -> k3 on default stream. Graph-capturable, no alloc.
// ============================================================================
extern "C" void kernel_launch(void* const* d_in, const int* in_sizes, int n_in,
                              void* d_out, int out_size) {
    const float* q = (const float*)d_in[0];
    const float* k = (const float*)d_in[1];
    const float* v = (const float*)d_in[2];
    const float* lgg = (const float*)d_in[n_in - 4];
    const float* ltg = (const float*)d_in[n_in - 3];
    const float* lgd = (const float*)d_in[n_in - 2];
    const float* ltd = (const float*)d_in[n_in - 1];

    const long V_ELEMS   = (long)2 * LLEN * 8 * 64;     // 1,048,576
    const long ATT_ELEMS = (long)NBH * LLEN * LLEN;     // 16,777,216
    const long ENT_ELEMS = (long)NBH * LLEN;            // 16,384

    float* out = (float*)d_out;
    float* vptr = out;
    float* attp;
    float* entp;
    if ((long)out_size >= V_ELEMS + ATT_ELEMS + ENT_ELEMS) {
        attp = out + V_ELEMS;
        entp = out + V_ELEMS + ATT_ELEMS;
    } else {
        void* p1 = nullptr; void* p2 = nullptr;
        cudaGetSymbolAddress(&p1, g_att_fb);
        cudaGetSymbolAddress(&p2, g_ent_fb);
        attp = (float*)p1;
        entp = (float*)p2;
    }

    kA<<<dim3(136, 16), 128>>>(q, k, attp, lgg, ltg, lgd, ltd);
    k3_av<<<dim3(8, 16), 128>>>(attp, v, vptr, entp);
}